// round 12
// baseline (speedup 1.0000x reference)
#include <cuda_runtime.h>
#include <cuda_bf16.h>
#include <cstdint>

// ===================== constants =====================

static constexpr int C = 256;               // feature dim
static constexpr int GRID_G = 152;          // 1 CTA / SM
static constexpr int TPB_G = 512;
static constexpr int CHUNK = 64;            // rows of A per pass
static constexpr int NQE = 3 * 128 * 128;   // 49152 interaction elems (3 quadrants)

static constexpr int T_STRIDE = 528;        // bf16 tile row stride (512 data + 16 pad)
static constexpr int T_BYTES = CHUNK * T_STRIDE;       // 33792
static constexpr int STAGE_BYTES = CHUNK * C * 4;      // 65536 (fp32 staging)
static constexpr int DSMEM = 1024 + STAGE_BYTES + 2 * T_BYTES;  // 134144

__device__ __nv_bfloat16 g_partial[(size_t)GRID_G * NQE];   // per-CTA partials (~14.9 MB)
__device__ float g_sq[NQE];

// ===================== PTX helpers (base ISA, valid on .target sm_103) ===========

__device__ __forceinline__ uint32_t smem_u32(const void* p) {
    uint32_t a;
    asm("{ .reg .u64 t; cvta.to.shared.u64 t, %1; cvt.u32.u64 %0, t; }" : "=r"(a) : "l"(p));
    return a;
}

__device__ __forceinline__ void ldsm_x4_trans(uint32_t* r, uint32_t addr) {
    asm volatile("ldmatrix.sync.aligned.m8n8.x4.trans.shared.b16 {%0,%1,%2,%3}, [%4];"
                 : "=r"(r[0]), "=r"(r[1]), "=r"(r[2]), "=r"(r[3]) : "r"(addr) : "memory");
}

__device__ __forceinline__ void mma16816(float* d, const uint32_t* a, const uint32_t* b) {
    asm volatile("mma.sync.aligned.m16n8k16.row.col.f32.bf16.bf16.f32 "
                 "{%0,%1,%2,%3}, {%4,%5,%6,%7}, {%8,%9}, {%0,%1,%2,%3};"
                 : "+f"(d[0]), "+f"(d[1]), "+f"(d[2]), "+f"(d[3])
                 : "r"(a[0]), "r"(a[1]), "r"(a[2]), "r"(a[3]), "r"(b[0]), "r"(b[1]));
}

__device__ __forceinline__ void cp_async16(uint32_t saddr, const void* gaddr) {
    asm volatile("cp.async.cg.shared.global [%0], [%1], 16;" :: "r"(saddr), "l"(gaddr) : "memory");
}
__device__ __forceinline__ void cp_commit() {
    asm volatile("cp.async.commit_group;" ::: "memory");
}
__device__ __forceinline__ void cp_wait0() {
    asm volatile("cp.async.wait_group 0;" ::: "memory");
}

__device__ __forceinline__ void lds_f32x4(float4& f, uint32_t addr) {
    asm volatile("ld.shared.v4.f32 {%0,%1,%2,%3}, [%4];"
                 : "=f"(f.x), "=f"(f.y), "=f"(f.z), "=f"(f.w) : "r"(addr) : "memory");
}
__device__ __forceinline__ void sts_b32x2(uint32_t addr, uint32_t a, uint32_t b) {
    asm volatile("st.shared.v2.b32 [%0], {%1,%2};" :: "r"(addr), "r"(a), "r"(b) : "memory");
}

// ===================== kernel 1: fused A^T A (mma.sync, reg acc) + E = A copy ==========
//
// Output = 3 stacked 128x128 quadrants of the symmetric A^T A (D00, D01, D11),
// viewed as a 384x128 matrix. 16 warps tile it as 8 row-slabs (48 rows = 3 x m16
// subtiles) x 2 col-slabs (n64). One n64 B-slab load per warp per k-step serves
// all 3 subtiles (2 loads only when the 48-slab crosses a quadrant boundary).

__global__ void __launch_bounds__(TPB_G, 1)
k_gemm_copy(const float* __restrict__ A, float* __restrict__ E, int Mrows) {
    extern __shared__ char dsm[];
    const uint32_t s0 = smem_u32(dsm);
    const uint32_t Sb = (s0 + 1023u) & ~1023u;                 // fp32 stage base
    const uint32_t Tb0 = Sb + (uint32_t)STAGE_BYTES;           // bf16 tile buf 0
    const uint32_t Tb1 = Tb0 + (uint32_t)T_BYTES;              // bf16 tile buf 1

    const int tid = threadIdx.x;
    const int wid = tid >> 5;
    const int lane = tid & 31;

    const int nchunks = Mrows / CHUNK;                         // 4096
    const int bid = blockIdx.x, stride = gridDim.x;
    const int nch = (nchunks - bid + stride - 1) / stride;

    // streaming role: coalesced — lane-consecutive 16B units of a row
    const int rsub = tid >> 6;            // 0..7: row subgroup
    const int ucol = tid & 63;            // 16B unit within row

    // --- warp subtile geometry (stacked 384x128, slab = 48 rows) ---
    const int rs = wid >> 1;              // row slab 0..7
    const int j0 = (wid & 1) * 64;        // col slab
    int quad[3], i0g[3], Abase[3], Bbase[3];
#pragma unroll
    for (int s = 0; s < 3; s++) {
        const int r0 = rs * 48 + s * 16;
        quad[s]  = r0 >> 7;               // 0: D00, 1: D01, 2: D11
        i0g[s]   = r0 & 127;
        Abase[s] = (quad[s] == 2 ? 128 : 0) + i0g[s];   // T row range of A operand
        Bbase[s] = (quad[s] >= 1 ? 128 : 0) + j0;       // T row range of B operand
    }
    const bool dualB = (Bbase[2] != Bbase[0]);

    // register accumulators: 3 subtiles x (m16 x n64)
    float acc[3][32];
#pragma unroll
    for (int s = 0; s < 3; s++)
#pragma unroll
        for (int r = 0; r < 32; r++) acc[s][r] = 0.0f;

    // ldmatrix / mma lane roles
    const int sel = lane >> 3, l7 = lane & 7;
    const int a_krow = l7 + ((sel >> 1) << 3);
    const int a_cofs = (sel & 1) << 3;
    const int b_krow = l7 + ((sel & 1) << 3);
    const int b_cofs = (sel >> 1) << 3;
    const int cr = lane >> 2, ctg = lane & 3;

    auto produce = [&](int g) {          // cp.async chunk g -> stage
        const float* __restrict__ src = A + ((size_t)g * CHUNK) * C;
#pragma unroll
        for (int k = 0; k < 8; k++) {
            const int row = k * 8 + rsub;
            cp_async16(Sb + (uint32_t)(row * 1024 + ucol * 16),
                       src + (size_t)row * C + ucol * 4);
        }
        cp_commit();
    };

    auto consume = [&](int g, uint32_t Tb) {   // stage -> E (fp32) + T (bf16)
        float* __restrict__ dst = E + ((size_t)g * CHUNK) * C;
#pragma unroll
        for (int k = 0; k < 8; k++) {
            const int row = k * 8 + rsub;
            float4 f;
            lds_f32x4(f, Sb + (uint32_t)(row * 1024 + ucol * 16));
            reinterpret_cast<float4*>(dst + (size_t)row * C)[ucol] = f;
            __nv_bfloat162 h0 = __floats2bfloat162_rn(f.x, f.y);
            __nv_bfloat162 h1 = __floats2bfloat162_rn(f.z, f.w);
            uint32_t p0, p1;
            memcpy(&p0, &h0, 4); memcpy(&p1, &h1, 4);
            sts_b32x2(Tb + (uint32_t)(row * T_STRIDE + ucol * 8), p0, p1);
        }
    };

    auto mma_phase = [&](uint32_t Tb) {
#pragma unroll
        for (int ks = 0; ks < 4; ks++) {
            const int k0 = ks * 16;
            // A fragments: one per subtile
            uint32_t a[3][4];
#pragma unroll
            for (int s = 0; s < 3; s++)
                ldsm_x4_trans(a[s], Tb + (uint32_t)((k0 + a_krow) * T_STRIDE
                                                    + (Abase[s] + a_cofs) * 2));
            // B slab(s): shared across subtiles
#pragma unroll
            for (int np = 0; np < 4; np++) {
                uint32_t b0[4], b1[4];
                ldsm_x4_trans(b0, Tb + (uint32_t)((k0 + b_krow) * T_STRIDE
                                                  + (Bbase[0] + np * 16 + b_cofs) * 2));
                if (dualB)
                    ldsm_x4_trans(b1, Tb + (uint32_t)((k0 + b_krow) * T_STRIDE
                                                      + (Bbase[2] + np * 16 + b_cofs) * 2));
#pragma unroll
                for (int s = 0; s < 3; s++) {
                    const uint32_t* bb = (dualB && Bbase[s] != Bbase[0]) ? b1 : b0;
                    mma16816(&acc[s][np * 8 + 0], a[s], &bb[0]);
                    mma16816(&acc[s][np * 8 + 4], a[s], &bb[2]);
                }
            }
        }
    };

    // ---- pipeline ----
    int g = bid;
    produce(g);
    cp_wait0();
    consume(g, Tb0);
    __syncthreads();

    for (int it = 0; it < nch; ++it) {
        const uint32_t Tb = (it & 1) ? Tb1 : Tb0;
        const bool more = (it + 1 < nch);
        if (more) produce(g + stride);             // overlaps mma below
        mma_phase(Tb);
        if (more) {
            cp_wait0();
            consume(g + stride, (it & 1) ? Tb0 : Tb1);
        }
        __syncthreads();
        g += stride;
    }

    // ---- flush register accumulators -> per-CTA bf16 partials [q][i][j] ----
    __nv_bfloat16* __restrict__ dst = g_partial + (size_t)bid * NQE;
#pragma unroll
    for (int s = 0; s < 3; s++) {
        __nv_bfloat16* qb = dst + quad[s] * 16384;
#pragma unroll
        for (int np = 0; np < 4; np++) {
#pragma unroll
            for (int h = 0; h < 2; h++) {
                const int col = j0 + np * 16 + h * 8 + ctg * 2;
                const float* a4 = &acc[s][np * 8 + h * 4];
                __nv_bfloat162 p0 = __floats2bfloat162_rn(a4[0], a4[1]);
                __nv_bfloat162 p1 = __floats2bfloat162_rn(a4[2], a4[3]);
                *reinterpret_cast<__nv_bfloat162*>(qb + (i0g[s] + cr) * 128 + col) = p0;
                *reinterpret_cast<__nv_bfloat162*>(qb + (i0g[s] + cr + 8) * 128 + col) = p1;
            }
        }
    }
}

// ===================== kernel 2: reduce bf16 partials over CTAs =====================

__global__ void k_reduce() {
    const int idx2 = blockIdx.x * blockDim.x + threadIdx.x;   // pair index < 24576
    float s0 = 0.0f, s1 = 0.0f;
    const __nv_bfloat162* __restrict__ p =
        reinterpret_cast<const __nv_bfloat162*>(g_partial) + idx2;
#pragma unroll 4
    for (int c = 0; c < GRID_G; ++c) {
        float2 f = __bfloat1622float2(p[(size_t)c * (NQE / 2)]);
        s0 += f.x; s1 += f.y;
    }
    g_sq[idx2 * 2 + 0] = s0;
    g_sq[idx2 * 2 + 1] = s1;
}

// ===================== kernel 3: row softmax -> CAG =====================

__global__ void k_softmax(float* __restrict__ cag) {
    const int c = blockIdx.x;       // row
    const int d = threadIdx.x;      // col
    const int wid = d >> 5, lane = d & 31;

    float v;
    if (c < 128) {
        v = (d < 128) ? g_sq[c * 128 + d]
                      : g_sq[16384 + c * 128 + (d - 128)];
    } else {
        v = (d < 128) ? g_sq[16384 + d * 128 + (c - 128)]    // symmetry
                      : g_sq[32768 + (c - 128) * 128 + (d - 128)];
    }

    __shared__ float red[8];
    float x = v;
#pragma unroll
    for (int o = 16; o > 0; o >>= 1) x = fmaxf(x, __shfl_xor_sync(0xFFFFFFFFu, x, o));
    if (lane == 0) red[wid] = x;
    __syncthreads();
    float mx = red[0];
#pragma unroll
    for (int i = 1; i < 8; i++) mx = fmaxf(mx, red[i]);
    __syncthreads();

    const float e = expf(v - mx);
    float s = e;
#pragma unroll
    for (int o = 16; o > 0; o >>= 1) s += __shfl_xor_sync(0xFFFFFFFFu, s, o);
    if (lane == 0) red[wid] = s;
    __syncthreads();
    float sum = red[0];
#pragma unroll
    for (int i = 1; i < 8; i++) sum += red[i];

    cag[c * 256 + d] = e / sum;
}

// ===================== kernel 4: beta != 0 fallback (early-exits for beta==0) ===========

__global__ void k_beta_fallback(const float* __restrict__ A,
                                const float* __restrict__ beta,
                                float* __restrict__ out, int Mrows) {
    const float b = beta[0];
    if (b == 0.0f) return;   // E = A already written; beta * temp == 0 exactly

    const float* __restrict__ cag = out + (size_t)Mrows * C;
    const size_t total = (size_t)Mrows * C;
    const size_t gstride = (size_t)gridDim.x * blockDim.x;
    for (size_t i = (size_t)blockIdx.x * blockDim.x + threadIdx.x; i < total; i += gstride) {
        const int mm = (int)(i >> 8);
        const int cc = (int)(i & 255);
        const float* a = A + (size_t)mm * C;
        const float* gg = cag + (size_t)cc * C;
        float t = 0.0f;
        for (int dd = 0; dd < C; ++dd) t += a[dd] * gg[dd];
        out[i] = a[cc] + b * t;
    }
}

// ===================== launch =====================

extern "C" void kernel_launch(void* const* d_in, const int* in_sizes, int n_in,
                              void* d_out, int out_size) {
    const float* A    = (const float*)d_in[0];
    const float* beta = (const float*)d_in[1];
    float* out        = (float*)d_out;

    const int Mrows = in_sizes[0] / C;          // 262144
    float* E   = out;
    float* cag = out + (size_t)Mrows * C;

    static bool attr_set = false;
    if (!attr_set) {
        cudaFuncSetAttribute(k_gemm_copy, cudaFuncAttributeMaxDynamicSharedMemorySize, DSMEM);
        attr_set = true;
    }

    k_gemm_copy<<<GRID_G, TPB_G, DSMEM>>>(A, E, Mrows);
    k_reduce<<<(NQE / 2) / 256, 256>>>();
    k_softmax<<<256, 256>>>(cag);
    k_beta_fallback<<<296, 256>>>(A, beta, out, Mrows);
}

// round 13
// speedup vs baseline: 1.0002x; 1.0002x over previous
#include <cuda_runtime.h>
#include <cuda_bf16.h>
#include <cstdint>

// ===================== constants =====================

static constexpr int C = 256;               // feature dim
static constexpr int GRID_G = 152;          // 1 CTA / SM
static constexpr int TPB_G = 512;
static constexpr int CHUNK = 64;            // rows of A per pass
static constexpr int NQE = 3 * 128 * 128;   // 49152 interaction elems (3 quadrants)

static constexpr int T_STRIDE = 528;        // bf16 tile row stride (512 data + 16 pad)
static constexpr int T_BYTES = CHUNK * T_STRIDE;       // 33792
static constexpr int STAGE_BYTES = CHUNK * C * 4;      // 65536 (fp32 staging)
static constexpr int DSMEM = 1024 + STAGE_BYTES + 2 * T_BYTES;  // 134144

__device__ __nv_bfloat16 g_partial[(size_t)GRID_G * NQE];   // per-CTA partials (~14.9 MB)
__device__ float g_sq[NQE];

// ===================== PTX helpers (base ISA, valid on .target sm_103) ===========

__device__ __forceinline__ uint32_t smem_u32(const void* p) {
    uint32_t a;
    asm("{ .reg .u64 t; cvta.to.shared.u64 t, %1; cvt.u32.u64 %0, t; }" : "=r"(a) : "l"(p));
    return a;
}

__device__ __forceinline__ void ldsm_x4_trans(uint32_t* r, uint32_t addr) {
    asm volatile("ldmatrix.sync.aligned.m8n8.x4.trans.shared.b16 {%0,%1,%2,%3}, [%4];"
                 : "=r"(r[0]), "=r"(r[1]), "=r"(r[2]), "=r"(r[3]) : "r"(addr) : "memory");
}

__device__ __forceinline__ void mma16816(float* d, const uint32_t* a, const uint32_t* b) {
    asm volatile("mma.sync.aligned.m16n8k16.row.col.f32.bf16.bf16.f32 "
                 "{%0,%1,%2,%3}, {%4,%5,%6,%7}, {%8,%9}, {%0,%1,%2,%3};"
                 : "+f"(d[0]), "+f"(d[1]), "+f"(d[2]), "+f"(d[3])
                 : "r"(a[0]), "r"(a[1]), "r"(a[2]), "r"(a[3]), "r"(b[0]), "r"(b[1]));
}

__device__ __forceinline__ void cp_async16(uint32_t saddr, const void* gaddr) {
    asm volatile("cp.async.cg.shared.global [%0], [%1], 16;" :: "r"(saddr), "l"(gaddr) : "memory");
}
__device__ __forceinline__ void cp_commit() {
    asm volatile("cp.async.commit_group;" ::: "memory");
}
__device__ __forceinline__ void cp_wait0() {
    asm volatile("cp.async.wait_group 0;" ::: "memory");
}

__device__ __forceinline__ void lds_f32x4(float4& f, uint32_t addr) {
    asm volatile("ld.shared.v4.f32 {%0,%1,%2,%3}, [%4];"
                 : "=f"(f.x), "=f"(f.y), "=f"(f.z), "=f"(f.w) : "r"(addr) : "memory");
}
__device__ __forceinline__ void sts_b32x2(uint32_t addr, uint32_t a, uint32_t b) {
    asm volatile("st.shared.v2.b32 [%0], {%1,%2};" :: "r"(addr), "r"(a), "r"(b) : "memory");
}

// ===================== kernel 1: fused A^T A (mma.sync, reg acc) + E = A copy ==========
//
// Output = 3 stacked 128x128 quadrants of the symmetric A^T A (D00, D01, D11),
// viewed as a 384x128 matrix. 16 warps tile it as 8 row-slabs (48 rows = 3 x m16
// subtiles) x 2 col-slabs (n64). One n64 B-slab load per warp per k-step serves
// all 3 subtiles (2 loads only when the 48-slab crosses a quadrant boundary).

__global__ void __launch_bounds__(TPB_G, 1)
k_gemm_copy(const float* __restrict__ A, float* __restrict__ E, int Mrows) {
    extern __shared__ char dsm[];
    const uint32_t s0 = smem_u32(dsm);
    const uint32_t Sb = (s0 + 1023u) & ~1023u;                 // fp32 stage base
    const uint32_t Tb0 = Sb + (uint32_t)STAGE_BYTES;           // bf16 tile buf 0
    const uint32_t Tb1 = Tb0 + (uint32_t)T_BYTES;              // bf16 tile buf 1

    const int tid = threadIdx.x;
    const int wid = tid >> 5;
    const int lane = tid & 31;

    const int nchunks = Mrows / CHUNK;                         // 4096
    const int bid = blockIdx.x, stride = gridDim.x;
    const int nch = (nchunks - bid + stride - 1) / stride;

    // streaming role: coalesced — lane-consecutive 16B units of a row
    const int rsub = tid >> 6;            // 0..7: row subgroup
    const int ucol = tid & 63;            // 16B unit within row

    // --- warp subtile geometry (stacked 384x128, slab = 48 rows) ---
    const int rs = wid >> 1;              // row slab 0..7
    const int j0 = (wid & 1) * 64;        // col slab
    int quad[3], i0g[3], Abase[3], Bbase[3];
#pragma unroll
    for (int s = 0; s < 3; s++) {
        const int r0 = rs * 48 + s * 16;
        quad[s]  = r0 >> 7;               // 0: D00, 1: D01, 2: D11
        i0g[s]   = r0 & 127;
        Abase[s] = (quad[s] == 2 ? 128 : 0) + i0g[s];   // T row range of A operand
        Bbase[s] = (quad[s] >= 1 ? 128 : 0) + j0;       // T row range of B operand
    }
    const bool dualB = (Bbase[2] != Bbase[0]);

    // register accumulators: 3 subtiles x (m16 x n64)
    float acc[3][32];
#pragma unroll
    for (int s = 0; s < 3; s++)
#pragma unroll
        for (int r = 0; r < 32; r++) acc[s][r] = 0.0f;

    // ldmatrix / mma lane roles
    const int sel = lane >> 3, l7 = lane & 7;
    const int a_krow = l7 + ((sel >> 1) << 3);
    const int a_cofs = (sel & 1) << 3;
    const int b_krow = l7 + ((sel & 1) << 3);
    const int b_cofs = (sel >> 1) << 3;
    const int cr = lane >> 2, ctg = lane & 3;

    auto produce = [&](int g) {          // cp.async chunk g -> stage
        const float* __restrict__ src = A + ((size_t)g * CHUNK) * C;
#pragma unroll
        for (int k = 0; k < 8; k++) {
            const int row = k * 8 + rsub;
            cp_async16(Sb + (uint32_t)(row * 1024 + ucol * 16),
                       src + (size_t)row * C + ucol * 4);
        }
        cp_commit();
    };

    auto consume = [&](int g, uint32_t Tb) {   // stage -> E (fp32) + T (bf16)
        float* __restrict__ dst = E + ((size_t)g * CHUNK) * C;
#pragma unroll
        for (int k = 0; k < 8; k++) {
            const int row = k * 8 + rsub;
            float4 f;
            lds_f32x4(f, Sb + (uint32_t)(row * 1024 + ucol * 16));
            reinterpret_cast<float4*>(dst + (size_t)row * C)[ucol] = f;
            __nv_bfloat162 h0 = __floats2bfloat162_rn(f.x, f.y);
            __nv_bfloat162 h1 = __floats2bfloat162_rn(f.z, f.w);
            uint32_t p0, p1;
            memcpy(&p0, &h0, 4); memcpy(&p1, &h1, 4);
            sts_b32x2(Tb + (uint32_t)(row * T_STRIDE + ucol * 8), p0, p1);
        }
    };

    auto mma_phase = [&](uint32_t Tb) {
#pragma unroll
        for (int ks = 0; ks < 4; ks++) {
            const int k0 = ks * 16;
            // A fragments: one per subtile
            uint32_t a[3][4];
#pragma unroll
            for (int s = 0; s < 3; s++)
                ldsm_x4_trans(a[s], Tb + (uint32_t)((k0 + a_krow) * T_STRIDE
                                                    + (Abase[s] + a_cofs) * 2));
            // B slab(s): shared across subtiles
#pragma unroll
            for (int np = 0; np < 4; np++) {
                uint32_t b0[4], b1[4];
                ldsm_x4_trans(b0, Tb + (uint32_t)((k0 + b_krow) * T_STRIDE
                                                  + (Bbase[0] + np * 16 + b_cofs) * 2));
                if (dualB)
                    ldsm_x4_trans(b1, Tb + (uint32_t)((k0 + b_krow) * T_STRIDE
                                                      + (Bbase[2] + np * 16 + b_cofs) * 2));
#pragma unroll
                for (int s = 0; s < 3; s++) {
                    const uint32_t* bb = (dualB && Bbase[s] != Bbase[0]) ? b1 : b0;
                    mma16816(&acc[s][np * 8 + 0], a[s], &bb[0]);
                    mma16816(&acc[s][np * 8 + 4], a[s], &bb[2]);
                }
            }
        }
    };

    // ---- pipeline ----
    int g = bid;
    produce(g);
    cp_wait0();
    consume(g, Tb0);
    __syncthreads();

    for (int it = 0; it < nch; ++it) {
        const uint32_t Tb = (it & 1) ? Tb1 : Tb0;
        const bool more = (it + 1 < nch);
        if (more) produce(g + stride);             // overlaps mma below
        mma_phase(Tb);
        if (more) {
            cp_wait0();
            consume(g + stride, (it & 1) ? Tb0 : Tb1);
        }
        __syncthreads();
        g += stride;
    }

    // ---- flush register accumulators -> per-CTA bf16 partials [q][i][j] ----
    __nv_bfloat16* __restrict__ dst = g_partial + (size_t)bid * NQE;
#pragma unroll
    for (int s = 0; s < 3; s++) {
        __nv_bfloat16* qb = dst + quad[s] * 16384;
#pragma unroll
        for (int np = 0; np < 4; np++) {
#pragma unroll
            for (int h = 0; h < 2; h++) {
                const int col = j0 + np * 16 + h * 8 + ctg * 2;
                const float* a4 = &acc[s][np * 8 + h * 4];
                __nv_bfloat162 p0 = __floats2bfloat162_rn(a4[0], a4[1]);
                __nv_bfloat162 p1 = __floats2bfloat162_rn(a4[2], a4[3]);
                *reinterpret_cast<__nv_bfloat162*>(qb + (i0g[s] + cr) * 128 + col) = p0;
                *reinterpret_cast<__nv_bfloat162*>(qb + (i0g[s] + cr + 8) * 128 + col) = p1;
            }
        }
    }
}

// ===================== kernel 2: reduce bf16 partials over CTAs =====================

__global__ void k_reduce() {
    const int idx2 = blockIdx.x * blockDim.x + threadIdx.x;   // pair index < 24576
    float s0 = 0.0f, s1 = 0.0f;
    const __nv_bfloat162* __restrict__ p =
        reinterpret_cast<const __nv_bfloat162*>(g_partial) + idx2;
#pragma unroll 4
    for (int c = 0; c < GRID_G; ++c) {
        float2 f = __bfloat1622float2(p[(size_t)c * (NQE / 2)]);
        s0 += f.x; s1 += f.y;
    }
    g_sq[idx2 * 2 + 0] = s0;
    g_sq[idx2 * 2 + 1] = s1;
}

// ===================== kernel 3: row softmax -> CAG =====================

__global__ void k_softmax(float* __restrict__ cag) {
    const int c = blockIdx.x;       // row
    const int d = threadIdx.x;      // col
    const int wid = d >> 5, lane = d & 31;

    float v;
    if (c < 128) {
        v = (d < 128) ? g_sq[c * 128 + d]
                      : g_sq[16384 + c * 128 + (d - 128)];
    } else {
        v = (d < 128) ? g_sq[16384 + d * 128 + (c - 128)]    // symmetry
                      : g_sq[32768 + (c - 128) * 128 + (d - 128)];
    }

    __shared__ float red[8];
    float x = v;
#pragma unroll
    for (int o = 16; o > 0; o >>= 1) x = fmaxf(x, __shfl_xor_sync(0xFFFFFFFFu, x, o));
    if (lane == 0) red[wid] = x;
    __syncthreads();
    float mx = red[0];
#pragma unroll
    for (int i = 1; i < 8; i++) mx = fmaxf(mx, red[i]);
    __syncthreads();

    const float e = expf(v - mx);
    float s = e;
#pragma unroll
    for (int o = 16; o > 0; o >>= 1) s += __shfl_xor_sync(0xFFFFFFFFu, s, o);
    if (lane == 0) red[wid] = s;
    __syncthreads();
    float sum = red[0];
#pragma unroll
    for (int i = 1; i < 8; i++) sum += red[i];

    cag[c * 256 + d] = e / sum;
}

// ===================== kernel 4: beta != 0 fallback (early-exits for beta==0) ===========

__global__ void k_beta_fallback(const float* __restrict__ A,
                                const float* __restrict__ beta,
                                float* __restrict__ out, int Mrows) {
    const float b = beta[0];
    if (b == 0.0f) return;   // E = A already written; beta * temp == 0 exactly

    const float* __restrict__ cag = out + (size_t)Mrows * C;
    const size_t total = (size_t)Mrows * C;
    const size_t gstride = (size_t)gridDim.x * blockDim.x;
    for (size_t i = (size_t)blockIdx.x * blockDim.x + threadIdx.x; i < total; i += gstride) {
        const int mm = (int)(i >> 8);
        const int cc = (int)(i & 255);
        const float* a = A + (size_t)mm * C;
        const float* gg = cag + (size_t)cc * C;
        float t = 0.0f;
        for (int dd = 0; dd < C; ++dd) t += a[dd] * gg[dd];
        out[i] = a[cc] + b * t;
    }
}

// ===================== launch =====================

extern "C" void kernel_launch(void* const* d_in, const int* in_sizes, int n_in,
                              void* d_out, int out_size) {
    const float* A    = (const float*)d_in[0];
    const float* beta = (const float*)d_in[1];
    float* out        = (float*)d_out;

    const int Mrows = in_sizes[0] / C;          // 262144
    float* E   = out;
    float* cag = out + (size_t)Mrows * C;

    static bool attr_set = false;
    if (!attr_set) {
        cudaFuncSetAttribute(k_gemm_copy, cudaFuncAttributeMaxDynamicSharedMemorySize, DSMEM);
        attr_set = true;
    }

    k_gemm_copy<<<GRID_G, TPB_G, DSMEM>>>(A, E, Mrows);
    k_reduce<<<(NQE / 2) / 256, 256>>>();
    k_softmax<<<256, 256>>>(cag);
    k_beta_fallback<<<296, 256>>>(A, beta, out, Mrows);
}

// round 14
// speedup vs baseline: 1.0052x; 1.0050x over previous
#include <cuda_runtime.h>
#include <cuda_bf16.h>
#include <cstdint>

// ===================== constants =====================

static constexpr int C = 256;               // feature dim
static constexpr int GRID_G = 152;          // 1 CTA / SM
static constexpr int TPB_G = 512;
static constexpr int CHUNK = 64;            // rows of A per pass
static constexpr int NQE = 3 * 128 * 128;   // 49152 interaction elems (3 quadrants)

static constexpr int T_STRIDE = 528;        // bf16 tile row stride (512 data + 16 pad)
static constexpr int T_BYTES = CHUNK * T_STRIDE;       // 33792
static constexpr int STAGE_BYTES = CHUNK * C * 4;      // 65536 (fp32 staging)
static constexpr int DSMEM = 1024 + STAGE_BYTES + 2 * T_BYTES;  // 134144

__device__ __nv_bfloat16 g_partial[(size_t)GRID_G * NQE];   // per-CTA partials (~14.9 MB)
__device__ float g_sq[NQE];

// ===================== PTX helpers (base ISA, valid on .target sm_103) ===========

__device__ __forceinline__ uint32_t smem_u32(const void* p) {
    uint32_t a;
    asm("{ .reg .u64 t; cvta.to.shared.u64 t, %1; cvt.u32.u64 %0, t; }" : "=r"(a) : "l"(p));
    return a;
}

__device__ __forceinline__ void ldsm_x4_trans(uint32_t* r, uint32_t addr) {
    asm volatile("ldmatrix.sync.aligned.m8n8.x4.trans.shared.b16 {%0,%1,%2,%3}, [%4];"
                 : "=r"(r[0]), "=r"(r[1]), "=r"(r[2]), "=r"(r[3]) : "r"(addr) : "memory");
}

__device__ __forceinline__ void mma16816(float* d, const uint32_t* a, const uint32_t* b) {
    asm volatile("mma.sync.aligned.m16n8k16.row.col.f32.bf16.bf16.f32 "
                 "{%0,%1,%2,%3}, {%4,%5,%6,%7}, {%8,%9}, {%0,%1,%2,%3};"
                 : "+f"(d[0]), "+f"(d[1]), "+f"(d[2]), "+f"(d[3])
                 : "r"(a[0]), "r"(a[1]), "r"(a[2]), "r"(a[3]), "r"(b[0]), "r"(b[1]));
}

__device__ __forceinline__ void cp_async16(uint32_t saddr, const void* gaddr) {
    asm volatile("cp.async.cg.shared.global [%0], [%1], 16;" :: "r"(saddr), "l"(gaddr) : "memory");
}
__device__ __forceinline__ void cp_commit() {
    asm volatile("cp.async.commit_group;" ::: "memory");
}
__device__ __forceinline__ void cp_wait0() {
    asm volatile("cp.async.wait_group 0;" ::: "memory");
}

__device__ __forceinline__ void lds_f32x4(float4& f, uint32_t addr) {
    asm volatile("ld.shared.v4.f32 {%0,%1,%2,%3}, [%4];"
                 : "=f"(f.x), "=f"(f.y), "=f"(f.z), "=f"(f.w) : "r"(addr) : "memory");
}
__device__ __forceinline__ void sts_b32x2(uint32_t addr, uint32_t a, uint32_t b) {
    asm volatile("st.shared.v2.b32 [%0], {%1,%2};" :: "r"(addr), "r"(a), "r"(b) : "memory");
}

// ===================== kernel 1: fused A^T A (mma.sync, reg acc) + E = A copy ==========
//
// Output = 3 stacked 128x128 quadrants of the symmetric A^T A (D00, D01, D11),
// viewed as a 384x128 matrix. 16 warps tile it as 8 row-slabs (48 rows = 3 x m16
// subtiles) x 2 col-slabs (n64). One n64 B-slab load per warp per k-step serves
// all 3 subtiles (2 loads only when the 48-slab crosses a quadrant boundary).

__global__ void __launch_bounds__(TPB_G, 1)
k_gemm_copy(const float* __restrict__ A, float* __restrict__ E, int Mrows) {
    extern __shared__ char dsm[];
    const uint32_t s0 = smem_u32(dsm);
    const uint32_t Sb = (s0 + 1023u) & ~1023u;                 // fp32 stage base
    const uint32_t Tb0 = Sb + (uint32_t)STAGE_BYTES;           // bf16 tile buf 0
    const uint32_t Tb1 = Tb0 + (uint32_t)T_BYTES;              // bf16 tile buf 1

    const int tid = threadIdx.x;
    const int wid = tid >> 5;
    const int lane = tid & 31;

    const int nchunks = Mrows / CHUNK;                         // 4096
    const int bid = blockIdx.x, stride = gridDim.x;
    const int nch = (nchunks - bid + stride - 1) / stride;

    // streaming role: coalesced — lane-consecutive 16B units of a row
    const int rsub = tid >> 6;            // 0..7: row subgroup
    const int ucol = tid & 63;            // 16B unit within row

    // --- warp subtile geometry (stacked 384x128, slab = 48 rows) ---
    const int rs = wid >> 1;              // row slab 0..7
    const int j0 = (wid & 1) * 64;        // col slab
    int quad[3], i0g[3], Abase[3], Bbase[3];
#pragma unroll
    for (int s = 0; s < 3; s++) {
        const int r0 = rs * 48 + s * 16;
        quad[s]  = r0 >> 7;               // 0: D00, 1: D01, 2: D11
        i0g[s]   = r0 & 127;
        Abase[s] = (quad[s] == 2 ? 128 : 0) + i0g[s];   // T row range of A operand
        Bbase[s] = (quad[s] >= 1 ? 128 : 0) + j0;       // T row range of B operand
    }
    const bool dualB = (Bbase[2] != Bbase[0]);

    // register accumulators: 3 subtiles x (m16 x n64)
    float acc[3][32];
#pragma unroll
    for (int s = 0; s < 3; s++)
#pragma unroll
        for (int r = 0; r < 32; r++) acc[s][r] = 0.0f;

    // ldmatrix / mma lane roles
    const int sel = lane >> 3, l7 = lane & 7;
    const int a_krow = l7 + ((sel >> 1) << 3);
    const int a_cofs = (sel & 1) << 3;
    const int b_krow = l7 + ((sel & 1) << 3);
    const int b_cofs = (sel >> 1) << 3;
    const int cr = lane >> 2, ctg = lane & 3;

    auto produce = [&](int g) {          // cp.async chunk g -> stage
        const float* __restrict__ src = A + ((size_t)g * CHUNK) * C;
#pragma unroll
        for (int k = 0; k < 8; k++) {
            const int row = k * 8 + rsub;
            cp_async16(Sb + (uint32_t)(row * 1024 + ucol * 16),
                       src + (size_t)row * C + ucol * 4);
        }
        cp_commit();
    };

    auto consume = [&](int g, uint32_t Tb) {   // stage -> E (fp32) + T (bf16)
        float* __restrict__ dst = E + ((size_t)g * CHUNK) * C;
#pragma unroll
        for (int k = 0; k < 8; k++) {
            const int row = k * 8 + rsub;
            float4 f;
            lds_f32x4(f, Sb + (uint32_t)(row * 1024 + ucol * 16));
            reinterpret_cast<float4*>(dst + (size_t)row * C)[ucol] = f;
            __nv_bfloat162 h0 = __floats2bfloat162_rn(f.x, f.y);
            __nv_bfloat162 h1 = __floats2bfloat162_rn(f.z, f.w);
            uint32_t p0, p1;
            memcpy(&p0, &h0, 4); memcpy(&p1, &h1, 4);
            sts_b32x2(Tb + (uint32_t)(row * T_STRIDE + ucol * 8), p0, p1);
        }
    };

    auto mma_phase = [&](uint32_t Tb) {
#pragma unroll
        for (int ks = 0; ks < 4; ks++) {
            const int k0 = ks * 16;
            // A fragments: one per subtile
            uint32_t a[3][4];
#pragma unroll
            for (int s = 0; s < 3; s++)
                ldsm_x4_trans(a[s], Tb + (uint32_t)((k0 + a_krow) * T_STRIDE
                                                    + (Abase[s] + a_cofs) * 2));
            // B slab(s): shared across subtiles
#pragma unroll
            for (int np = 0; np < 4; np++) {
                uint32_t b0[4], b1[4];
                ldsm_x4_trans(b0, Tb + (uint32_t)((k0 + b_krow) * T_STRIDE
                                                  + (Bbase[0] + np * 16 + b_cofs) * 2));
                if (dualB)
                    ldsm_x4_trans(b1, Tb + (uint32_t)((k0 + b_krow) * T_STRIDE
                                                      + (Bbase[2] + np * 16 + b_cofs) * 2));
#pragma unroll
                for (int s = 0; s < 3; s++) {
                    const uint32_t* bb = (dualB && Bbase[s] != Bbase[0]) ? b1 : b0;
                    mma16816(&acc[s][np * 8 + 0], a[s], &bb[0]);
                    mma16816(&acc[s][np * 8 + 4], a[s], &bb[2]);
                }
            }
        }
    };

    // ---- pipeline ----
    int g = bid;
    produce(g);
    cp_wait0();
    consume(g, Tb0);
    __syncthreads();

    for (int it = 0; it < nch; ++it) {
        const uint32_t Tb = (it & 1) ? Tb1 : Tb0;
        const bool more = (it + 1 < nch);
        if (more) produce(g + stride);             // overlaps mma below
        mma_phase(Tb);
        if (more) {
            cp_wait0();
            consume(g + stride, (it & 1) ? Tb0 : Tb1);
        }
        __syncthreads();
        g += stride;
    }

    // ---- flush register accumulators -> per-CTA bf16 partials [q][i][j] ----
    __nv_bfloat16* __restrict__ dst = g_partial + (size_t)bid * NQE;
#pragma unroll
    for (int s = 0; s < 3; s++) {
        __nv_bfloat16* qb = dst + quad[s] * 16384;
#pragma unroll
        for (int np = 0; np < 4; np++) {
#pragma unroll
            for (int h = 0; h < 2; h++) {
                const int col = j0 + np * 16 + h * 8 + ctg * 2;
                const float* a4 = &acc[s][np * 8 + h * 4];
                __nv_bfloat162 p0 = __floats2bfloat162_rn(a4[0], a4[1]);
                __nv_bfloat162 p1 = __floats2bfloat162_rn(a4[2], a4[3]);
                *reinterpret_cast<__nv_bfloat162*>(qb + (i0g[s] + cr) * 128 + col) = p0;
                *reinterpret_cast<__nv_bfloat162*>(qb + (i0g[s] + cr + 8) * 128 + col) = p1;
            }
        }
    }
}

// ===================== kernel 2: reduce bf16 partials over CTAs =====================

__global__ void k_reduce() {
    const int idx2 = blockIdx.x * blockDim.x + threadIdx.x;   // pair index < 24576
    float s0 = 0.0f, s1 = 0.0f;
    const __nv_bfloat162* __restrict__ p =
        reinterpret_cast<const __nv_bfloat162*>(g_partial) + idx2;
#pragma unroll 4
    for (int c = 0; c < GRID_G; ++c) {
        float2 f = __bfloat1622float2(p[(size_t)c * (NQE / 2)]);
        s0 += f.x; s1 += f.y;
    }
    g_sq[idx2 * 2 + 0] = s0;
    g_sq[idx2 * 2 + 1] = s1;
}

// ===================== kernel 3: row softmax -> CAG =====================

__global__ void k_softmax(float* __restrict__ cag) {
    const int c = blockIdx.x;       // row
    const int d = threadIdx.x;      // col
    const int wid = d >> 5, lane = d & 31;

    float v;
    if (c < 128) {
        v = (d < 128) ? g_sq[c * 128 + d]
                      : g_sq[16384 + c * 128 + (d - 128)];
    } else {
        v = (d < 128) ? g_sq[16384 + d * 128 + (c - 128)]    // symmetry
                      : g_sq[32768 + (c - 128) * 128 + (d - 128)];
    }

    __shared__ float red[8];
    float x = v;
#pragma unroll
    for (int o = 16; o > 0; o >>= 1) x = fmaxf(x, __shfl_xor_sync(0xFFFFFFFFu, x, o));
    if (lane == 0) red[wid] = x;
    __syncthreads();
    float mx = red[0];
#pragma unroll
    for (int i = 1; i < 8; i++) mx = fmaxf(mx, red[i]);
    __syncthreads();

    const float e = expf(v - mx);
    float s = e;
#pragma unroll
    for (int o = 16; o > 0; o >>= 1) s += __shfl_xor_sync(0xFFFFFFFFu, s, o);
    if (lane == 0) red[wid] = s;
    __syncthreads();
    float sum = red[0];
#pragma unroll
    for (int i = 1; i < 8; i++) sum += red[i];

    cag[c * 256 + d] = e / sum;
}

// ===================== kernel 4: beta != 0 fallback (early-exits for beta==0) ===========

__global__ void k_beta_fallback(const float* __restrict__ A,
                                const float* __restrict__ beta,
                                float* __restrict__ out, int Mrows) {
    const float b = beta[0];
    if (b == 0.0f) return;   // E = A already written; beta * temp == 0 exactly

    const float* __restrict__ cag = out + (size_t)Mrows * C;
    const size_t total = (size_t)Mrows * C;
    const size_t gstride = (size_t)gridDim.x * blockDim.x;
    for (size_t i = (size_t)blockIdx.x * blockDim.x + threadIdx.x; i < total; i += gstride) {
        const int mm = (int)(i >> 8);
        const int cc = (int)(i & 255);
        const float* a = A + (size_t)mm * C;
        const float* gg = cag + (size_t)cc * C;
        float t = 0.0f;
        for (int dd = 0; dd < C; ++dd) t += a[dd] * gg[dd];
        out[i] = a[cc] + b * t;
    }
}

// ===================== launch =====================

extern "C" void kernel_launch(void* const* d_in, const int* in_sizes, int n_in,
                              void* d_out, int out_size) {
    const float* A    = (const float*)d_in[0];
    const float* beta = (const float*)d_in[1];
    float* out        = (float*)d_out;

    const int Mrows = in_sizes[0] / C;          // 262144
    float* E   = out;
    float* cag = out + (size_t)Mrows * C;

    static bool attr_set = false;
    if (!attr_set) {
        cudaFuncSetAttribute(k_gemm_copy, cudaFuncAttributeMaxDynamicSharedMemorySize, DSMEM);
        attr_set = true;
    }

    k_gemm_copy<<<GRID_G, TPB_G, DSMEM>>>(A, E, Mrows);
    k_reduce<<<(NQE / 2) / 256, 256>>>();
    k_softmax<<<256, 256>>>(cag);
    k_beta_fallback<<<296, 256>>>(A, beta, out, Mrows);
}